// round 12
// baseline (speedup 1.0000x reference)
#include <cuda_runtime.h>
#include <cuda_bf16.h>
#include <math_constants.h>
#include <cstdint>

#define Np   8192
#define DP   128
#define DM   256
#define BM   8192           // B*M queries
#define NPT  32768          // B*Np distinct points
#define NROW 131072         // BM*16 (query,neighbor) rows
#define RES_ELEMS (BM*DP)

// ===================== PTX helpers (baseline sm_103) =====================
__device__ __forceinline__ uint32_t smem_u32(const void* p) {
    uint32_t a;
    asm("{ .reg .u64 t; cvta.to.shared.u64 t, %1; cvt.u32.u64 %0, t; }" : "=r"(a) : "l"(p));
    return a;
}
__device__ __forceinline__ void cpasync16(uint32_t dst, const void* src) {
    asm volatile("cp.async.cg.shared.global [%0], [%1], 16;" :: "r"(dst), "l"(src));
}
#define CP_COMMIT() asm volatile("cp.async.commit_group;" ::: "memory")
#define CP_WAIT(n)  asm volatile("cp.async.wait_group %0;" :: "n"(n) : "memory")

__device__ __forceinline__ void ldsm4(uint32_t* r, uint32_t addr) {
    asm volatile("ldmatrix.sync.aligned.m8n8.x4.shared.b16 {%0,%1,%2,%3}, [%4];"
        : "=r"(r[0]), "=r"(r[1]), "=r"(r[2]), "=r"(r[3]) : "r"(addr));
}
__device__ __forceinline__ void mma16816(float* c, const uint32_t* a, const uint32_t* b) {
    asm volatile("mma.sync.aligned.m16n8k16.row.col.f32.bf16.bf16.f32 "
        "{%0,%1,%2,%3}, {%4,%5,%6,%7}, {%8,%9}, {%0,%1,%2,%3};"
        : "+f"(c[0]), "+f"(c[1]), "+f"(c[2]), "+f"(c[3])
        : "r"(a[0]), "r"(a[1]), "r"(a[2]), "r"(a[3]), "r"(b[0]), "r"(b[1]));
}

// ===================== scratch =====================
__device__ int   g_knn[BM*16];
__device__ float g_q  [BM*DM];
__device__ float g_kpt[NPT*DM];
__device__ float g_vpt[NPT*DM];
__device__ float g_pos[NROW*DM];
__device__ __align__(16) __nv_bfloat16 g_qfh[BM*DP],  g_qfl[BM*DP];
__device__ __align__(16) __nv_bfloat16 g_fsh[NPT*DP], g_fsl[NPT*DP];
__device__ __align__(16) __nv_bfloat16 g_xph[NPT*DM], g_xpl[NPT*DM];
__device__ __align__(16) __nv_bfloat16 g_hhi[NROW*DM], g_hlo[NROW*DM];
__device__ __align__(16) __nv_bfloat16 g_ahi[NROW*DM], g_alo[NROW*DM];
// transposed+split weights [N=256][K]
__device__ __align__(16) __nv_bfloat16 w_qh[DM*DP],  w_ql[DM*DP];
__device__ __align__(16) __nv_bfloat16 w_f1h[DM*DP], w_f1l[DM*DP];
__device__ __align__(16) __nv_bfloat16 w_kh[DM*DM],  w_kl[DM*DM];
__device__ __align__(16) __nv_bfloat16 w_vh[DM*DM],  w_vl[DM*DM];
__device__ __align__(16) __nv_bfloat16 w_d2h[DM*DM], w_d2l[DM*DM];
__device__ __align__(16) __nv_bfloat16 w_g1h[DM*DM], w_g1l[DM*DM];
__device__ __align__(16) __nv_bfloat16 w_g2h[DM*DM], w_g2l[DM*DM];

// ===================== KNN =====================
__global__ void knn_kernel(const float* __restrict__ xyz,
                           const float* __restrict__ query) {
    int wip  = threadIdx.x >> 5;
    int lane = threadIdx.x & 31;
    int qi   = blockIdx.x * 8 + wip;
    int b    = qi >> 11;
    const float* qp = query + (size_t)qi * 131;
    float qx = qp[0], qy = qp[1], qz = qp[2];
    float q2 = qx*qx + qy*qy + qz*qz;
    const float* xb = xyz + (size_t)b * Np * 3;

    float bd[16]; int bi[16];
#pragma unroll
    for (int i = 0; i < 16; i++) { bd[i] = CUDART_INF_F; bi[i] = 0x7fffffff; }
    float cm = CUDART_INF_F; int cmp_ = 0;

    for (int n = lane; n < Np; n += 32) {
        float x = xb[3*n], y = xb[3*n+1], z = xb[3*n+2];
        float d = q2 + (x*x + y*y + z*z) - 2.0f*(qx*x + qy*y + qz*z);
        if (d < cm) {
#pragma unroll
            for (int i = 0; i < 16; i++) if (i == cmp_) { bd[i] = d; bi[i] = n; }
            cm = -CUDART_INF_F;
#pragma unroll
            for (int i = 0; i < 16; i++) if (bd[i] > cm) { cm = bd[i]; cmp_ = i; }
        }
    }
    for (int r = 0; r < 16; r++) {
        float md = CUDART_INF_F; int mi = 0x7fffffff;
#pragma unroll
        for (int i = 0; i < 16; i++) {
            float d = bd[i]; int id = bi[i];
            if (d < md || (d == md && id < mi)) { md = d; mi = id; }
        }
#pragma unroll
        for (int off = 16; off > 0; off >>= 1) {
            float od = __shfl_down_sync(0xffffffffu, md, off);
            int   oi = __shfl_down_sync(0xffffffffu, mi, off);
            if (od < md || (od == md && oi < mi)) { md = od; mi = oi; }
        }
        int w = __shfl_sync(0xffffffffu, mi, 0);
        if (lane == 0) g_knn[qi*16 + r] = w;
#pragma unroll
        for (int i = 0; i < 16; i++) if (bi[i] == w) bd[i] = CUDART_INF_F;
    }
}

// ===================== prep kernels =====================
__global__ void wprep_kernel(const float* __restrict__ W,
                             __nv_bfloat16* __restrict__ Th,
                             __nv_bfloat16* __restrict__ Tl, int K) {
    int i = blockIdx.x * 256 + threadIdx.x;
    if (i >= K * DM) return;
    int k = i / DM, n = i % DM;
    float v = W[i];
    __nv_bfloat16 h = __float2bfloat16(v);
    Th[n*K + k] = h;
    Tl[n*K + k] = __float2bfloat16(v - __bfloat162float(h));
}

__global__ void qsplit_kernel(const float* __restrict__ query,
                              __nv_bfloat16* __restrict__ qh,
                              __nv_bfloat16* __restrict__ ql) {
    int i = blockIdx.x * 256 + threadIdx.x;
    int r = i >> 7, c = i & 127;
    float v = query[(size_t)r*131 + 3 + c];
    __nv_bfloat16 h = __float2bfloat16(v);
    qh[i] = h;
    ql[i] = __float2bfloat16(v - __bfloat162float(h));
}

__global__ void fsplit_kernel(const float* __restrict__ feat,
                              __nv_bfloat16* __restrict__ fh,
                              __nv_bfloat16* __restrict__ fl) {
    int i = blockIdx.x * 256 + threadIdx.x;
    float v = feat[i];
    __nv_bfloat16 h = __float2bfloat16(v);
    fh[i] = h;
    fl[i] = __float2bfloat16(v - __bfloat162float(h));
}

__global__ __launch_bounds__(256) void hprep_kernel(const float* __restrict__ xyz,
                                                    const float* __restrict__ query,
                                                    const float* __restrict__ d1w,
                                                    const float* __restrict__ d1b) {
    __shared__ float sdel[16][4];
    int bm = blockIdx.x, b = bm >> 11, tid = threadIdx.x;
    if (tid < 16) {
        int idx = g_knn[bm*16 + tid];
        const float* qp = query + (size_t)bm*131;
        const float* xp = xyz + ((size_t)b*Np + idx)*3;
        sdel[tid][0] = qp[0] - xp[0];
        sdel[tid][1] = qp[1] - xp[1];
        sdel[tid][2] = qp[2] - xp[2];
    }
    __syncthreads();
    int c = tid;
    float w0 = d1w[c], w1 = d1w[DM + c], w2 = d1w[2*DM + c], bb = d1b[c];
#pragma unroll
    for (int r = 0; r < 16; r++) {
        float v = fmaxf(fmaf(sdel[r][2], w2, fmaf(sdel[r][1], w1, fmaf(sdel[r][0], w0, bb))), 0.f);
        size_t o = (size_t)(bm*16 + r)*DM + c;
        __nv_bfloat16 h = __float2bfloat16(v);
        g_hhi[o] = h;
        g_hlo[o] = __float2bfloat16(v - __bfloat162float(h));
    }
}

// ===================== shared GEMM machinery =====================
// stage layout (per stage): AH +0, AL +18432, BH +36864, BL +73728
#define AH_OFF 0
#define AL_OFF 18432
#define BH_OFF 36864
#define BL_OFF 73728
#define STG    110592
#define SMEM_TOTAL (2*STG)
// fused loop2 layout: 4 t-slots (36864 each, hi+lo) at c*36864; B buffer at:
#define SM_B2  147456

__device__ __forceinline__ void load_chunk(uint32_t sbase,
    const __nv_bfloat16* Ah, const __nv_bfloat16* Al,
    const __nv_bfloat16* Bh, const __nv_bfloat16* Bl,
    int tile, int Kdim, int kc0, int tid)
{
#pragma unroll
    for (int g = 0; g < 2; g++) {
        int e = g*512 + tid;
        int r = e >> 3, c = e & 7;
        size_t off = (size_t)(tile*128 + r)*Kdim + kc0 + c*8;
        cpasync16(sbase + AH_OFF + r*144 + c*16, Ah + off);
        cpasync16(sbase + AL_OFF + r*144 + c*16, Al + off);
    }
#pragma unroll
    for (int g = 0; g < 4; g++) {
        int e = g*512 + tid;
        int n = e >> 3, c = e & 7;
        size_t off = (size_t)n*Kdim + kc0 + c*8;
        cpasync16(sbase + BH_OFF + n*144 + c*16, Bh + off);
        cpasync16(sbase + BL_OFF + n*144 + c*16, Bl + off);
    }
}

// B-only load to a standalone B buffer (BH +0, BL +36864), K = DM
__device__ __forceinline__ void load_b2(uint32_t bbase,
    const __nv_bfloat16* Bh, const __nv_bfloat16* Bl, int kc0, int tid)
{
#pragma unroll
    for (int g = 0; g < 4; g++) {
        int e = g*512 + tid;
        int n = e >> 3, c = e & 7;
        size_t off = (size_t)n*DM + kc0 + c*8;
        cpasync16(bbase + n*144 + c*16, Bh + off);
        cpasync16(bbase + 36864 + n*144 + c*16, Bl + off);
    }
}

// mma over one 64-wide K chunk; A base (hi; lo at +18432), B base (hi; lo at +36864)
__device__ __forceinline__ void mma_chunk(uint32_t aB, uint32_t bB,
    uint32_t aRow, uint32_t aKoff, uint32_t bRow, uint32_t bKoff,
    int nbase, float (*acc)[8][4])
{
#pragma unroll
    for (int k16 = 0; k16 < 4; k16++) {
        uint32_t ah[2][4], alr[2][4];
        uint32_t ab = aB + aRow*144 + k16*32 + aKoff;
        ldsm4(ah[0], ab);
        ldsm4(ah[1], ab + 16*144);
        ldsm4(alr[0], ab + 18432);
        ldsm4(alr[1], ab + 18432 + 16*144);
#pragma unroll
        for (int np = 0; np < 4; np++) {
            uint32_t bh[4], bl[4];
            uint32_t bb = bB + (nbase + np*16 + bRow)*144 + k16*32 + bKoff;
            ldsm4(bh, bb);
            ldsm4(bl, bb + 36864);
#pragma unroll
            for (int mf = 0; mf < 2; mf++) {
                mma16816(acc[mf][2*np],   ah[mf],  bh);
                mma16816(acc[mf][2*np],   alr[mf], bh);
                mma16816(acc[mf][2*np],   ah[mf],  bl);
                mma16816(acc[mf][2*np+1], ah[mf],  bh + 2);
                mma16816(acc[mf][2*np+1], alr[mf], bh + 2);
                mma16816(acc[mf][2*np+1], ah[mf],  bl + 2);
            }
        }
    }
}

// ===================== generic GEMM (qproj / x / k / v / pos) ==============
// epi: 0 = fp32 -> outf
//      1 = split -> outh/outl
//      3 = pos-combined: outf=pos fp32; a = q[bm] - kpt[gather] + pos -> split
__global__ __launch_bounds__(512, 1) void tc_gemm(
    const __nv_bfloat16* __restrict__ Ahi, const __nv_bfloat16* __restrict__ Alo,
    const __nv_bfloat16* __restrict__ Bhi, const __nv_bfloat16* __restrict__ Blo,
    const float* __restrict__ bias,
    const float* __restrict__ qv, const float* __restrict__ kpt,
    float* __restrict__ outf,
    __nv_bfloat16* __restrict__ outh, __nv_bfloat16* __restrict__ outl,
    int Kdim, int epi_mode)
{
    extern __shared__ char dsm[];
    uint32_t sb = smem_u32(dsm);
    int tid = threadIdx.x, lid = tid & 31, wid = tid >> 5;
    int tile = blockIdx.x;
    int mw = wid & 3, nw = wid >> 2;
    int mbase = mw*32, nbase = nw*64;

    uint32_t aRow  = mbase + (lid & 15);
    uint32_t aKoff = ((lid >> 4) & 1) * 16;
    uint32_t bRow  = (lid & 7) + ((lid >> 4) & 1) * 8;
    uint32_t bKoff = ((lid >> 3) & 1) * 16;

    float acc[2][8][4];
#pragma unroll
    for (int i = 0; i < 2; i++)
#pragma unroll
        for (int j = 0; j < 8; j++)
#pragma unroll
            for (int e = 0; e < 4; e++) acc[i][j][e] = 0.f;

    const int nst = Kdim >> 6;
    load_chunk(sb, Ahi, Alo, Bhi, Blo, tile, Kdim, 0, tid);
    CP_COMMIT();

    for (int s = 0; s < nst; s++) {
        if (s + 1 < nst) {
            load_chunk(sb + ((s+1)&1)*STG, Ahi, Alo, Bhi, Blo, tile, Kdim, (s+1)*64, tid);
            CP_COMMIT();
            CP_WAIT(1);
        } else {
            CP_WAIT(0);
        }
        __syncthreads();
        uint32_t stb = sb + (s&1)*STG;
        mma_chunk(stb + AH_OFF, stb + BH_OFF, aRow, aKoff, bRow, bKoff, nbase, acc);
        __syncthreads();
    }

    float* eb = (float*)dsm;   // [128][264]
#pragma unroll
    for (int mf = 0; mf < 2; mf++)
#pragma unroll
        for (int nf = 0; nf < 8; nf++) {
            int m = mbase + mf*16 + (lid >> 2);
            int n = nbase + nf*8 + (lid & 3)*2;
            eb[m*264 + n]     = acc[mf][nf][0];
            eb[m*264 + n + 1] = acc[mf][nf][1];
            eb[(m+8)*264 + n]     = acc[mf][nf][2];
            eb[(m+8)*264 + n + 1] = acc[mf][nf][3];
        }
    __syncthreads();

    for (int i = tid; i < 128*256; i += 512) {
        int row = i >> 8, col = i & 255;
        float v = eb[row*264 + col];
        if (bias) v += bias[col];
        size_t o = (size_t)(tile*128 + row) * DM + col;
        if (epi_mode == 0) {
            outf[o] = v;
        } else if (epi_mode == 1) {
            __nv_bfloat16 h = __float2bfloat16(v);
            outh[o] = h; outl[o] = __float2bfloat16(v - __bfloat162float(h));
        } else {  // pos-combined
            outf[o] = v;
            int row_g = tile*128 + row;
            int bm = row_g >> 4, j = row_g & 15, b = bm >> 11;
            int idx = g_knn[bm*16 + j];
            float a = qv[(size_t)bm*DM + col]
                    - kpt[((size_t)b*Np + idx)*DM + col] + v;
            __nv_bfloat16 h = __float2bfloat16(a);
            outh[o] = h; outl[o] = __float2bfloat16(a - __bfloat162float(h));
        }
    }
}

// ===================== fused g1 -> g2 -> softmax/V/fc2/residual =============
__global__ __launch_bounds__(512, 1) void g1g2_fused(
    const __nv_bfloat16* __restrict__ Ahi, const __nv_bfloat16* __restrict__ Alo,
    const __nv_bfloat16* __restrict__ G1h, const __nv_bfloat16* __restrict__ G1l,
    const float* __restrict__ g1b,
    const __nv_bfloat16* __restrict__ G2h, const __nv_bfloat16* __restrict__ G2l,
    const float* __restrict__ g2b,
    const float* __restrict__ fc2w, const float* __restrict__ fc2b,
    const float* __restrict__ query,
    const float* __restrict__ vpt, const float* __restrict__ pos,
    float* __restrict__ out)
{
    extern __shared__ char dsm[];
    uint32_t sb = smem_u32(dsm);
    int tid = threadIdx.x, lid = tid & 31, wid = tid >> 5;
    int tile = blockIdx.x;
    int mw = wid & 3, nw = wid >> 2;
    int mbase = mw*32, nbase = nw*64;

    uint32_t aRow  = mbase + (lid & 15);
    uint32_t aKoff = ((lid >> 4) & 1) * 16;
    uint32_t bRow  = (lid & 7) + ((lid >> 4) & 1) * 8;
    uint32_t bKoff = ((lid >> 3) & 1) * 16;

    float acc[2][8][4];
#pragma unroll
    for (int i = 0; i < 2; i++)
#pragma unroll
        for (int j = 0; j < 8; j++)
#pragma unroll
            for (int e = 0; e < 4; e++) acc[i][j][e] = 0.f;

    // ---------------- loop1: t_pre = a @ g1 (K = 256) ----------------
    load_chunk(sb, Ahi, Alo, G1h, G1l, tile, DM, 0, tid);
    CP_COMMIT();
    for (int s = 0; s < 4; s++) {
        if (s + 1 < 4) {
            load_chunk(sb + ((s+1)&1)*STG, Ahi, Alo, G1h, G1l, tile, DM, (s+1)*64, tid);
            CP_COMMIT();
            CP_WAIT(1);
        } else {
            CP_WAIT(0);
        }
        __syncthreads();
        uint32_t stb = sb + (s&1)*STG;
        mma_chunk(stb + AH_OFF, stb + BH_OFF, aRow, aKoff, bRow, bKoff, nbase, acc);
        __syncthreads();
    }
    // all smem now dead; acc holds t_pre

    // ---- prefetch g2 B chunk 0 into the standalone B buffer (dead region)
    load_b2(sb + SM_B2, G2h, G2l, 0, tid);
    CP_COMMIT();

    // ---- stage ALL FOUR t chunks NOW, from live acc (warp nw -> slot nw).
    // slot c at dsm + c*36864: hi at +0, lo at +18432 (A-layout, 144B rows)
    {
        char* tA = dsm + nw*36864;
#pragma unroll
        for (int mf = 0; mf < 2; mf++)
#pragma unroll
            for (int nf = 0; nf < 8; nf++) {
                int r = mbase + mf*16 + (lid >> 2);
                int c = nf*8 + (lid & 3)*2;
                int gc = nbase + c;
                float v0 = fmaxf(acc[mf][nf][0] + g1b[gc],   0.f);
                float v1 = fmaxf(acc[mf][nf][1] + g1b[gc+1], 0.f);
                float v2 = fmaxf(acc[mf][nf][2] + g1b[gc],   0.f);
                float v3 = fmaxf(acc[mf][nf][3] + g1b[gc+1], 0.f);
                __nv_bfloat162 hp, lp;
                hp.x = __float2bfloat16(v0); hp.y = __float2bfloat16(v1);
                lp.x = __float2bfloat16(v0 - __bfloat162float(hp.x));
                lp.y = __float2bfloat16(v1 - __bfloat162float(hp.y));
                *(uint32_t*)(tA + r*144 + c*2)         = *(uint32_t*)&hp;
                *(uint32_t*)(tA + 18432 + r*144 + c*2) = *(uint32_t*)&lp;
                hp.x = __float2bfloat16(v2); hp.y = __float2bfloat16(v3);
                lp.x = __float2bfloat16(v2 - __bfloat162float(hp.x));
                lp.y = __float2bfloat16(v3 - __bfloat162float(hp.y));
                *(uint32_t*)(tA + (r+8)*144 + c*2)         = *(uint32_t*)&hp;
                *(uint32_t*)(tA + 18432 + (r+8)*144 + c*2) = *(uint32_t*)&lp;
            }
    }

    // reset accumulators for g2 (t is fully in smem now)
#pragma unroll
    for (int i = 0; i < 2; i++)
#pragma unroll
        for (int j = 0; j < 8; j++)
#pragma unroll
            for (int e = 0; e < 4; e++) acc[i][j][e] = 0.f;

    // ---------------- loop2: attn_pre = t @ g2 (K = 256), single-buffer B --
    for (int c4 = 0; c4 < 4; c4++) {
        CP_WAIT(0);
        __syncthreads();     // B chunk visible + t STS visible (first iter)
        mma_chunk(sb + c4*36864, sb + SM_B2, aRow, aKoff, bRow, bKoff, nbase, acc);
        __syncthreads();     // all reads of B buffer done before overwrite
        if (c4 < 3) {
            load_b2(sb + SM_B2, G2h, G2l, (c4+1)*64, tid);
            CP_COMMIT();
        }
    }

    // ---------------- epilogue: stage attn_pre, softmax, V, fc2, residual ---
    float* eb   = (float*)dsm;                 // [128][264]  (135168 B)
    float* sres = (float*)(dsm + 139264);      // [8][256]    (8192 B)
    int*   sidx = (int*)  (dsm + 147456);      // [128]
#pragma unroll
    for (int mf = 0; mf < 2; mf++)
#pragma unroll
        for (int nf = 0; nf < 8; nf++) {
            int m = mbase + mf*16 + (lid >> 2);
            int n = nbase + nf*8 + (lid & 3)*2;
            eb[m*264 + n]     = acc[mf][nf][0];
            eb[m*264 + n + 1] = acc[mf][nf][1];
            eb[(m+8)*264 + n]     = acc[mf][nf][2];
            eb[(m+8)*264 + n + 1] = acc[mf][nf][3];
        }
    int bm0 = tile * 8;
    if (tid < 128) sidx[tid] = g_knn[(bm0 + (tid >> 4))*16 + (tid & 15)];
    __syncthreads();

    {
        int qq = tid >> 6, c0 = tid & 63;
        int bm = bm0 + qq, b = bm >> 11;
        float* attn_out = out + RES_ELEMS + (size_t)bm*16*DM;
#pragma unroll
        for (int jj = 0; jj < 4; jj++) {
            int col = c0 + 64*jj;
            float bb = g2b[col];
            float ap[16];
#pragma unroll
            for (int j = 0; j < 16; j++)
                ap[j] = (eb[(qq*16 + j)*264 + col] + bb) * 0.0625f;
            float mx = ap[0];
#pragma unroll
            for (int j = 1; j < 16; j++) mx = fmaxf(mx, ap[j]);
            float s = 0.f;
#pragma unroll
            for (int j = 0; j < 16; j++) { ap[j] = __expf(ap[j] - mx); s += ap[j]; }
            float inv = 1.0f / s;
            float racc = 0.f;
#pragma unroll
            for (int j = 0; j < 16; j++) {
                float a = ap[j] * inv;
                attn_out[j*DM + col] = a;
                float vv = vpt[((size_t)b*Np + sidx[qq*16 + j])*DM + col];
                float pp = pos[((size_t)(tile*128 + qq*16 + j))*DM + col];
                racc = fmaf(a, vv + pp, racc);
            }
            sres[qq*256 + col] = racc;
        }
    }
    __syncthreads();

    for (int o = tid; o < 8*DP; o += 512) {
        int qq = o >> 7, c = o & 127;
        float acc2 = fc2b[c];
        const float* sr = sres + qq*256;
#pragma unroll 4
        for (int k = 0; k < DM; k++) acc2 = fmaf(sr[k], fc2w[k*DP + c], acc2);
        int bm = bm0 + qq;
        out[(size_t)bm*DP + c] = acc2 + query[(size_t)bm*131 + 3 + c];
    }
}

// ===================== launch =====================
extern "C" void kernel_launch(void* const* d_in, const int* in_sizes, int n_in,
                              void* d_out, int out_size) {
    const float* xyz   = (const float*)d_in[0];
    const float* feat  = (const float*)d_in[1];
    const float* query = (const float*)d_in[2];
    const float* fc1w  = (const float*)d_in[3];
    const float* fc1b  = (const float*)d_in[4];
    const float* fc2w  = (const float*)d_in[5];
    const float* fc2b  = (const float*)d_in[6];
    const float* d1w   = (const float*)d_in[7];
    const float* d1b   = (const float*)d_in[8];
    const float* d2w   = (const float*)d_in[9];
    const float* d2b   = (const float*)d_in[10];
    const float* g1w   = (const float*)d_in[11];
    const float* g1b   = (const float*)d_in[12];
    const float* g2w   = (const float*)d_in[13];
    const float* g2b   = (const float*)d_in[14];
    const float* wq    = (const float*)d_in[15];
    const float* wk    = (const float*)d_in[16];
    const float* wv    = (const float*)d_in[17];
    float* out = (float*)d_out;

    static int smem_set = 0;
    if (!smem_set) {
        cudaFuncSetAttribute(tc_gemm,    cudaFuncAttributeMaxDynamicSharedMemorySize, SMEM_TOTAL);
        cudaFuncSetAttribute(g1g2_fused, cudaFuncAttributeMaxDynamicSharedMemorySize, SMEM_TOTAL);
        smem_set = 1;
    }

    __nv_bfloat16 *p_qh, *p_ql, *p_f1h, *p_f1l, *p_kh, *p_kl, *p_vh, *p_vl,
                  *p_d2h, *p_d2l, *p_g1h, *p_g1l, *p_g2h, *p_g2l;
    cudaGetSymbolAddress((void**)&p_qh,  w_qh);  cudaGetSymbolAddress((void**)&p_ql,  w_ql);
    cudaGetSymbolAddress((void**)&p_f1h, w_f1h); cudaGetSymbolAddress((void**)&p_f1l, w_f1l);
    cudaGetSymbolAddress((void**)&p_kh,  w_kh);  cudaGetSymbolAddress((void**)&p_kl,  w_kl);
    cudaGetSymbolAddress((void**)&p_vh,  w_vh);  cudaGetSymbolAddress((void**)&p_vl,  w_vl);
    cudaGetSymbolAddress((void**)&p_d2h, w_d2h); cudaGetSymbolAddress((void**)&p_d2l, w_d2l);
    cudaGetSymbolAddress((void**)&p_g1h, w_g1h); cudaGetSymbolAddress((void**)&p_g1l, w_g1l);
    cudaGetSymbolAddress((void**)&p_g2h, w_g2h); cudaGetSymbolAddress((void**)&p_g2l, w_g2l);
    float *p_q, *p_kp, *p_vp, *p_pos;
    __nv_bfloat16 *p_qfh, *p_qfl, *p_fsh, *p_fsl, *p_xh, *p_xl, *p_hh, *p_hl,
                  *p_ah, *p_al;
    cudaGetSymbolAddress((void**)&p_q,   g_q);
    cudaGetSymbolAddress((void**)&p_kp,  g_kpt);
    cudaGetSymbolAddress((void**)&p_vp,  g_vpt);
    cudaGetSymbolAddress((void**)&p_pos, g_pos);
    cudaGetSymbolAddress((void**)&p_qfh, g_qfh); cudaGetSymbolAddress((void**)&p_qfl, g_qfl);
    cudaGetSymbolAddress((void**)&p_fsh, g_fsh); cudaGetSymbolAddress((void**)&p_fsl, g_fsl);
    cudaGetSymbolAddress((void**)&p_xh,  g_xph); cudaGetSymbolAddress((void**)&p_xl,  g_xpl);
    cudaGetSymbolAddress((void**)&p_hh,  g_hhi); cudaGetSymbolAddress((void**)&p_hl,  g_hlo);
    cudaGetSymbolAddress((void**)&p_ah,  g_ahi); cudaGetSymbolAddress((void**)&p_al,  g_alo);

    knn_kernel<<<BM/8, 256>>>(xyz, query);

    wprep_kernel<<<DP, 256>>>(wq,   p_qh,  p_ql,  DP);
    wprep_kernel<<<DP, 256>>>(fc1w, p_f1h, p_f1l, DP);
    wprep_kernel<<<DM, 256>>>(wk,   p_kh,  p_kl,  DM);
    wprep_kernel<<<DM, 256>>>(wv,   p_vh,  p_vl,  DM);
    wprep_kernel<<<DM, 256>>>(d2w,  p_d2h, p_d2l, DM);
    wprep_kernel<<<DM, 256>>>(g1w,  p_g1h, p_g1l, DM);
    wprep_kernel<<<DM, 256>>>(g2w,  p_g2h, p_g2l, DM);

    qsplit_kernel<<<BM*DP/256, 256>>>(query, p_qfh, p_qfl);
    fsplit_kernel<<<NPT*DP/256, 256>>>(feat, p_fsh, p_fsl);
    hprep_kernel <<<BM, 256>>>(xyz, query, d1w, d1b);

    // q = query_f @ wq                     (8192 rows, fp32 -> g_q)
    tc_gemm<<<BM/128, 512, SMEM_TOTAL>>>(p_qfh, p_qfl, p_qh, p_ql,
        nullptr, nullptr, nullptr, p_q, nullptr, nullptr, DP, 0);
    // x_pt = feat @ fc1 + b                (32768 rows, split)
    tc_gemm<<<NPT/128, 512, SMEM_TOTAL>>>(p_fsh, p_fsl, p_f1h, p_f1l,
        fc1b, nullptr, nullptr, nullptr, p_xh, p_xl, DP, 1);
    // k_pt = x_pt @ wk                     (32768 rows, fp32)
    tc_gemm<<<NPT/128, 512, SMEM_TOTAL>>>(p_xh, p_xl, p_kh, p_kl,
        nullptr, nullptr, nullptr, p_kp, nullptr, nullptr, DM, 0);
    // v_pt = x_pt @ wv                     (32768 rows, fp32)
    tc_gemm<<<NPT/128, 512, SMEM_TOTAL>>>(p_xh, p_xl, p_vh, p_vl,
        nullptr, nullptr, nullptr, p_vp, nullptr, nullptr, DM, 0);
    // pos = h @ d2 + b; a = q - k[gather] + pos   (131072 rows)
    tc_gemm<<<NROW/128, 512, SMEM_TOTAL>>>(p_hh, p_hl, p_d2h, p_d2l,
        d2b, p_q, p_kp, p_pos, p_ah, p_al, DM, 3);
    // fused: t = relu(a@g1+b); attn_pre = t@g2+b; softmax; res; fc2; residual
    g1g2_fused<<<NROW/128, 512, SMEM_TOTAL>>>(p_ah, p_al, p_g1h, p_g1l, g1b,
        p_g2h, p_g2l, g2b, fc2w, fc2b, query, p_vp, p_pos, out);
}

// round 13
// speedup vs baseline: 1.1035x; 1.1035x over previous
#include <cuda_runtime.h>
#include <cuda_fp16.h>
#include <math_constants.h>
#include <cstdint>

#define Np   8192
#define DP   128
#define DM   256
#define BM   8192           // B*M queries
#define NPT  32768          // B*Np distinct points
#define NROW 131072         // BM*16 (query,neighbor) rows
#define RES_ELEMS (BM*DP)

// ===================== PTX helpers (baseline sm_103) =====================
__device__ __forceinline__ uint32_t smem_u32(const void* p) {
    uint32_t a;
    asm("{ .reg .u64 t; cvta.to.shared.u64 t, %1; cvt.u32.u64 %0, t; }" : "=r"(a) : "l"(p));
    return a;
}
__device__ __forceinline__ void cpasync16(uint32_t dst, const void* src) {
    asm volatile("cp.async.cg.shared.global [%0], [%1], 16;" :: "r"(dst), "l"(src));
}
#define CP_COMMIT() asm volatile("cp.async.commit_group;" ::: "memory")
#define CP_WAIT(n)  asm volatile("cp.async.wait_group %0;" :: "n"(n) : "memory")

__device__ __forceinline__ void ldsm4(uint32_t* r, uint32_t addr) {
    asm volatile("ldmatrix.sync.aligned.m8n8.x4.shared.b16 {%0,%1,%2,%3}, [%4];"
        : "=r"(r[0]), "=r"(r[1]), "=r"(r[2]), "=r"(r[3]) : "r"(addr));
}
__device__ __forceinline__ void mma16816(float* c, const uint32_t* a, const uint32_t* b) {
    asm volatile("mma.sync.aligned.m16n8k16.row.col.f32.f16.f16.f32 "
        "{%0,%1,%2,%3}, {%4,%5,%6,%7}, {%8,%9}, {%0,%1,%2,%3};"
        : "+f"(c[0]), "+f"(c[1]), "+f"(c[2]), "+f"(c[3])
        : "r"(a[0]), "r"(a[1]), "r"(a[2]), "r"(a[3]), "r"(b[0]), "r"(b[1]));
}

// ===================== scratch =====================
__device__ int   g_knn[BM*16];
__device__ float g_q  [BM*DM];
__device__ float g_kpt[NPT*DM];
__device__ float g_vpt[NPT*DM];
__device__ float g_pos[NROW*DM];
__device__ __align__(16) __half g_qfh[BM*DP],  g_qfl[BM*DP];
__device__ __align__(16) __half g_fsh[NPT*DP], g_fsl[NPT*DP];
__device__ __align__(16) __half g_xph[NPT*DM], g_xpl[NPT*DM];
__device__ __align__(16) __half g_hhi[NROW*DM], g_hlo[NROW*DM];
__device__ __align__(16) __half g_ahi[NROW*DM], g_alo[NROW*DM];
// transposed fp16 weights [N=256][K]
__device__ __align__(16) __half w_q [DM*DP];
__device__ __align__(16) __half w_f1[DM*DP];
__device__ __align__(16) __half w_k [DM*DM];
__device__ __align__(16) __half w_v [DM*DM];
__device__ __align__(16) __half w_d2[DM*DM];
__device__ __align__(16) __half w_g1[DM*DM];
__device__ __align__(16) __half w_g2[DM*DM];

// ===================== KNN =====================
__global__ void knn_kernel(const float* __restrict__ xyz,
                           const float* __restrict__ query) {
    int wip  = threadIdx.x >> 5;
    int lane = threadIdx.x & 31;
    int qi   = blockIdx.x * 8 + wip;
    int b    = qi >> 11;
    const float* qp = query + (size_t)qi * 131;
    float qx = qp[0], qy = qp[1], qz = qp[2];
    float q2 = qx*qx + qy*qy + qz*qz;
    const float* xb = xyz + (size_t)b * Np * 3;

    float bd[16]; int bi[16];
#pragma unroll
    for (int i = 0; i < 16; i++) { bd[i] = CUDART_INF_F; bi[i] = 0x7fffffff; }
    float cm = CUDART_INF_F; int cmp_ = 0;

    for (int n = lane; n < Np; n += 32) {
        float x = xb[3*n], y = xb[3*n+1], z = xb[3*n+2];
        float d = q2 + (x*x + y*y + z*z) - 2.0f*(qx*x + qy*y + qz*z);
        if (d < cm) {
#pragma unroll
            for (int i = 0; i < 16; i++) if (i == cmp_) { bd[i] = d; bi[i] = n; }
            cm = -CUDART_INF_F;
#pragma unroll
            for (int i = 0; i < 16; i++) if (bd[i] > cm) { cm = bd[i]; cmp_ = i; }
        }
    }
    for (int r = 0; r < 16; r++) {
        float md = CUDART_INF_F; int mi = 0x7fffffff;
#pragma unroll
        for (int i = 0; i < 16; i++) {
            float d = bd[i]; int id = bi[i];
            if (d < md || (d == md && id < mi)) { md = d; mi = id; }
        }
#pragma unroll
        for (int off = 16; off > 0; off >>= 1) {
            float od = __shfl_down_sync(0xffffffffu, md, off);
            int   oi = __shfl_down_sync(0xffffffffu, mi, off);
            if (od < md || (od == md && oi < mi)) { md = od; mi = oi; }
        }
        int w = __shfl_sync(0xffffffffu, mi, 0);
        if (lane == 0) g_knn[qi*16 + r] = w;
#pragma unroll
        for (int i = 0; i < 16; i++) if (bi[i] == w) bd[i] = CUDART_INF_F;
    }
}

// ===================== prep kernels =====================
__global__ void wprep_kernel(const float* __restrict__ W,
                             __half* __restrict__ T, int K) {
    int i = blockIdx.x * 256 + threadIdx.x;
    if (i >= K * DM) return;
    int k = i / DM, n = i % DM;
    T[n*K + k] = __float2half_rn(W[i]);
}

__global__ void qsplit_kernel(const float* __restrict__ query,
                              __half* __restrict__ qh,
                              __half* __restrict__ ql) {
    int i = blockIdx.x * 256 + threadIdx.x;
    int r = i >> 7, c = i & 127;
    float v = query[(size_t)r*131 + 3 + c];
    __half h = __float2half_rn(v);
    qh[i] = h;
    ql[i] = __float2half_rn(v - __half2float(h));
}

__global__ void fsplit_kernel(const float* __restrict__ feat,
                              __half* __restrict__ fh,
                              __half* __restrict__ fl) {
    int i = blockIdx.x * 256 + threadIdx.x;
    float v = feat[i];
    __half h = __float2half_rn(v);
    fh[i] = h;
    fl[i] = __float2half_rn(v - __half2float(h));
}

__global__ __launch_bounds__(256) void hprep_kernel(const float* __restrict__ xyz,
                                                    const float* __restrict__ query,
                                                    const float* __restrict__ d1w,
                                                    const float* __restrict__ d1b) {
    __shared__ float sdel[16][4];
    int bm = blockIdx.x, b = bm >> 11, tid = threadIdx.x;
    if (tid < 16) {
        int idx = g_knn[bm*16 + tid];
        const float* qp = query + (size_t)bm*131;
        const float* xp = xyz + ((size_t)b*Np + idx)*3;
        sdel[tid][0] = qp[0] - xp[0];
        sdel[tid][1] = qp[1] - xp[1];
        sdel[tid][2] = qp[2] - xp[2];
    }
    __syncthreads();
    int c = tid;
    float w0 = d1w[c], w1 = d1w[DM + c], w2 = d1w[2*DM + c], bb = d1b[c];
#pragma unroll
    for (int r = 0; r < 16; r++) {
        float v = fmaxf(fmaf(sdel[r][2], w2, fmaf(sdel[r][1], w1, fmaf(sdel[r][0], w0, bb))), 0.f);
        size_t o = (size_t)(bm*16 + r)*DM + c;
        __half h = __float2half_rn(v);
        g_hhi[o] = h;
        g_hlo[o] = __float2half_rn(v - __half2float(h));
    }
}

// ===================== shared GEMM machinery (fp16, 2-term) ================
// stage layout: AH +0 (18432), AL +18432 (18432), B +36864 (36864)
#define AL_OFF 18432
#define B_OFF  36864
#define STG    73728
#define SMEM_TOTAL (3*STG)          // 221184
// fused loop2: 4 t-slots (hi+lo 36864 each) at c*36864; B dbl-buf at:
#define SM_B2  147456

__device__ __forceinline__ void load_chunk(uint32_t sbase,
    const __half* Ah, const __half* Al, const __half* B,
    int tile, int Kdim, int kc0, int tid)
{
#pragma unroll
    for (int g = 0; g < 2; g++) {
        int e = g*512 + tid;
        int r = e >> 3, c = e & 7;
        size_t off = (size_t)(tile*128 + r)*Kdim + kc0 + c*8;
        cpasync16(sbase + r*144 + c*16, Ah + off);
        cpasync16(sbase + AL_OFF + r*144 + c*16, Al + off);
    }
#pragma unroll
    for (int g = 0; g < 4; g++) {
        int e = g*512 + tid;
        int n = e >> 3, c = e & 7;
        size_t off = (size_t)n*Kdim + kc0 + c*8;
        cpasync16(sbase + B_OFF + n*144 + c*16, B + off);
    }
}

// B-only load (K = DM)
__device__ __forceinline__ void load_b2(uint32_t bbase,
    const __half* B, int kc0, int tid)
{
#pragma unroll
    for (int g = 0; g < 4; g++) {
        int e = g*512 + tid;
        int n = e >> 3, c = e & 7;
        size_t off = (size_t)n*DM + kc0 + c*8;
        cpasync16(bbase + n*144 + c*16, B + off);
    }
}

// mma over one 64-wide K chunk; A at aB (hi; lo at +18432), B at bB
__device__ __forceinline__ void mma_chunk(uint32_t aB, uint32_t bB,
    uint32_t aRow, uint32_t aKoff, uint32_t bRow, uint32_t bKoff,
    int nbase, float (*acc)[8][4])
{
#pragma unroll
    for (int k16 = 0; k16 < 4; k16++) {
        uint32_t ah[2][4], alr[2][4];
        uint32_t ab = aB + aRow*144 + k16*32 + aKoff;
        ldsm4(ah[0], ab);
        ldsm4(ah[1], ab + 16*144);
        ldsm4(alr[0], ab + AL_OFF);
        ldsm4(alr[1], ab + AL_OFF + 16*144);
#pragma unroll
        for (int np = 0; np < 4; np++) {
            uint32_t bh[4];
            ldsm4(bh, bB + (nbase + np*16 + bRow)*144 + k16*32 + bKoff);
#pragma unroll
            for (int mf = 0; mf < 2; mf++) {
                mma16816(acc[mf][2*np],   ah[mf],  bh);
                mma16816(acc[mf][2*np],   alr[mf], bh);
                mma16816(acc[mf][2*np+1], ah[mf],  bh + 2);
                mma16816(acc[mf][2*np+1], alr[mf], bh + 2);
            }
        }
    }
}

// ===================== generic GEMM (qproj / x / k / v / pos) ==============
// epi: 0 = fp32 -> outf
//      1 = split -> outh/outl
//      3 = pos-combined: outf=pos fp32; a = q[bm] - kpt[gather] + pos -> split
__global__ __launch_bounds__(512, 1) void tc_gemm(
    const __half* __restrict__ Ahi, const __half* __restrict__ Alo,
    const __half* __restrict__ Bw,
    const float* __restrict__ bias,
    const float* __restrict__ qv, const float* __restrict__ kpt,
    float* __restrict__ outf,
    __half* __restrict__ outh, __half* __restrict__ outl,
    int Kdim, int epi_mode)
{
    extern __shared__ char dsm[];
    uint32_t sb = smem_u32(dsm);
    int tid = threadIdx.x, lid = tid & 31, wid = tid >> 5;
    int tile = blockIdx.x;
    int mw = wid & 3, nw = wid >> 2;
    int mbase = mw*32, nbase = nw*64;

    uint32_t aRow  = mbase + (lid & 15);
    uint32_t aKoff = ((lid >> 4) & 1) * 16;
    uint32_t bRow  = (lid & 7) + ((lid >> 4) & 1) * 8;
    uint32_t bKoff = ((lid >> 3) & 1) * 16;

    float acc[2][8][4];
#pragma unroll
    for (int i = 0; i < 2; i++)
#pragma unroll
        for (int j = 0; j < 8; j++)
#pragma unroll
            for (int e = 0; e < 4; e++) acc[i][j][e] = 0.f;

    const int nst = Kdim >> 6;
    load_chunk(sb, Ahi, Alo, Bw, tile, Kdim, 0, tid);
    CP_COMMIT();
    if (nst > 1) {
        load_chunk(sb + STG, Ahi, Alo, Bw, tile, Kdim, 64, tid);
        CP_COMMIT();
    }

    for (int s = 0; s < nst; s++) {
        if (s + 2 < nst) {
            load_chunk(sb + ((s+2)%3)*STG, Ahi, Alo, Bw, tile, Kdim, (s+2)*64, tid);
            CP_COMMIT();
            CP_WAIT(2);
        } else if (s + 1 < nst) {
            CP_WAIT(1);
        } else {
            CP_WAIT(0);
        }
        __syncthreads();
        uint32_t stb = sb + (s%3)*STG;
        mma_chunk(stb, stb + B_OFF, aRow, aKoff, bRow, bKoff, nbase, acc);
        __syncthreads();
    }

    float* eb = (float*)dsm;   // [128][264]
#pragma unroll
    for (int mf = 0; mf < 2; mf++)
#pragma unroll
        for (int nf = 0; nf < 8; nf++) {
            int m = mbase + mf*16 + (lid >> 2);
            int n = nbase + nf*8 + (lid & 3)*2;
            eb[m*264 + n]     = acc[mf][nf][0];
            eb[m*264 + n + 1] = acc[mf][nf][1];
            eb[(m+8)*264 + n]     = acc[mf][nf][2];
            eb[(m+8)*264 + n + 1] = acc[mf][nf][3];
        }
    __syncthreads();

    for (int i = tid; i < 128*256; i += 512) {
        int row = i >> 8, col = i & 255;
        float v = eb[row*264 + col];
        if (bias) v += bias[col];
        size_t o = (size_t)(tile*128 + row) * DM + col;
        if (epi_mode == 0) {
            outf[o] = v;
        } else if (epi_mode == 1) {
            __half h = __float2half_rn(v);
            outh[o] = h; outl[o] = __float2half_rn(v - __half2float(h));
        } else {  // pos-combined
            outf[o] = v;
            int row_g = tile*128 + row;
            int bm = row_g >> 4, j = row_g & 15, b = bm >> 11;
            int idx = g_knn[bm*16 + j];
            float a = qv[(size_t)bm*DM + col]
                    - kpt[((size_t)b*Np + idx)*DM + col] + v;
            __half h = __float2half_rn(a);
            outh[o] = h; outl[o] = __float2half_rn(a - __half2float(h));
        }
    }
}

// ===================== fused g1 -> g2 -> softmax/V/fc2/residual =============
__global__ __launch_bounds__(512, 1) void g1g2_fused(
    const __half* __restrict__ Ahi, const __half* __restrict__ Alo,
    const __half* __restrict__ G1, const float* __restrict__ g1b,
    const __half* __restrict__ G2, const float* __restrict__ g2b,
    const float* __restrict__ fc2w, const float* __restrict__ fc2b,
    const float* __restrict__ query,
    const float* __restrict__ vpt, const float* __restrict__ pos,
    float* __restrict__ out)
{
    extern __shared__ char dsm[];
    uint32_t sb = smem_u32(dsm);
    int tid = threadIdx.x, lid = tid & 31, wid = tid >> 5;
    int tile = blockIdx.x;
    int mw = wid & 3, nw = wid >> 2;
    int mbase = mw*32, nbase = nw*64;

    uint32_t aRow  = mbase + (lid & 15);
    uint32_t aKoff = ((lid >> 4) & 1) * 16;
    uint32_t bRow  = (lid & 7) + ((lid >> 4) & 1) * 8;
    uint32_t bKoff = ((lid >> 3) & 1) * 16;

    float acc[2][8][4];
#pragma unroll
    for (int i = 0; i < 2; i++)
#pragma unroll
        for (int j = 0; j < 8; j++)
#pragma unroll
            for (int e = 0; e < 4; e++) acc[i][j][e] = 0.f;

    // ---------------- loop1: t_pre = a @ g1 (K = 256, 3-stage) -------------
    load_chunk(sb, Ahi, Alo, G1, tile, DM, 0, tid);
    CP_COMMIT();
    load_chunk(sb + STG, Ahi, Alo, G1, tile, DM, 64, tid);
    CP_COMMIT();
    for (int s = 0; s < 4; s++) {
        if (s + 2 < 4) {
            load_chunk(sb + ((s+2)%3)*STG, Ahi, Alo, G1, tile, DM, (s+2)*64, tid);
            CP_COMMIT();
            CP_WAIT(2);
        } else if (s + 1 < 4) {
            CP_WAIT(1);
        } else {
            CP_WAIT(0);
        }
        __syncthreads();
        uint32_t stb = sb + (s%3)*STG;
        mma_chunk(stb, stb + B_OFF, aRow, aKoff, bRow, bKoff, nbase, acc);
        __syncthreads();
    }
    // all smem dead; acc holds t_pre

    // ---- prefetch g2 B chunks 0,1 into double buffers (dead region)
    load_b2(sb + SM_B2,         G2, 0,  tid); CP_COMMIT();
    load_b2(sb + SM_B2 + 36864, G2, 64, tid); CP_COMMIT();

    // ---- stage ALL FOUR t chunks from live acc (warp-group nw -> slot nw)
    // slot c at dsm + c*36864: hi +0, lo +18432 (144B rows)
    {
        char* tA = dsm + nw*36864;
#pragma unroll
        for (int mf = 0; mf < 2; mf++)
#pragma unroll
            for (int nf = 0; nf < 8; nf++) {
                int r = mbase + mf*16 + (lid >> 2);
                int c = nf*8 + (lid & 3)*2;
                int gc = nbase + c;
                float v0 = fmaxf(acc[mf][nf][0] + g1b[gc],   0.f);
                float v1 = fmaxf(acc[mf][nf][1] + g1b[gc+1], 0.f);
                float v2 = fmaxf(acc[mf][nf][2] + g1b[gc],   0.f);
                float v3 = fmaxf(acc[mf][nf][3] + g1b[gc+1], 0.f);
                __half2 hp, lp;
                hp.x = __float2half_rn(v0); hp.y = __float2half_rn(v1);
                lp.x = __float2half_rn(v0 - __half2float(hp.x));
                lp.y = __float2half_rn(v1 - __half2float(hp.y));
                *(uint32_t*)(tA + r*144 + c*2)          = *(uint32_t*)&hp;
                *(uint32_t*)(tA + AL_OFF + r*144 + c*2) = *(uint32_t*)&lp;
                hp.x = __float2half_rn(v2); hp.y = __float2half_rn(v3);
                lp.x = __float2half_rn(v2 - __half2float(hp.x));
                lp.y = __float2half_rn(v3 - __half2float(hp.y));
                *(uint32_t*)(tA + (r+8)*144 + c*2)          = *(uint32_t*)&hp;
                *(uint32_t*)(tA + AL_OFF + (r+8)*144 + c*2) = *(uint32_t*)&lp;
            }
    }

    // reset accumulators for g2
#pragma unroll
    for (int i = 0; i < 2; i++)
#pragma unroll
        for (int j = 0; j < 8; j++)
#pragma unroll
            for (int e = 0; e < 4; e++) acc[i][j][e] = 0.f;

    // ---------------- loop2: attn_pre = t @ g2 (K = 256, dbl-buffered B) ---
    for (int c4 = 0; c4 < 4; c4++) {
        if (c4 < 3) { CP_WAIT(1); } else { CP_WAIT(0); }
        __syncthreads();     // B chunk visible + t STS visible (first iter)
        mma_chunk(sb + c4*36864, sb + SM_B2 + (c4&1)*36864,
                  aRow, aKoff, bRow, bKoff, nbase, acc);
        __syncthreads();
        if (c4 + 2 < 4) {
            load_b2(sb + SM_B2 + (c4&1)*36864, G2, (c4+2)*64, tid);
            CP_COMMIT();
        }
    }

    // ---------------- epilogue: stage attn_pre, softmax, V, fc2, residual ---
    float* eb   = (float*)dsm;                 // [128][264]  (135168 B)
    float* sres = (float*)(dsm + 139264);      // [8][256]    (8192 B)
    int*   sidx = (int*)  (dsm + 147456);      // [128]
#pragma unroll
    for (int mf = 0; mf < 2; mf++)
#pragma unroll
        for (int nf = 0; nf < 8; nf++) {
            int m = mbase + mf*16 + (lid >> 2);
            int n = nbase + nf*8 + (lid & 3)*2;
            eb[m*264 + n]     = acc[mf][nf][0];
            eb[m*264 + n + 1] = acc[mf][nf][1];
            eb[(m+8)*264 + n]     = acc[mf][nf][2];
            eb[(m+8)*264 + n + 1] = acc[mf][nf][3];
        }
    int bm0 = tile * 8;
    if (tid < 128) sidx[tid] = g_knn[(bm0 + (tid >> 4))*16 + (tid & 15)];
    __syncthreads();

    {
        int qq = tid >> 6, c0 = tid & 63;
        int bm = bm0 + qq, b = bm >> 11;
        float* attn_out = out + RES_ELEMS + (size_t)bm*16*DM;
#pragma unroll
        for (int jj = 0; jj < 4; jj++) {
            int col = c0 + 64*jj;
            float bb = g2b[col];
            float ap[16];
#pragma unroll
            for (int j = 0; j < 16; j++)
                ap[j] = (eb[(qq*16 + j)*264 + col] + bb) * 0.0625f;
            float mx = ap[0];
#pragma unroll
            for (int j = 1; j < 16; j++) mx = fmaxf(mx, ap[j]);
            float s = 0.f;
#pragma unroll
            for (int j = 0; j < 16; j++) { ap[j] = __expf(ap[j] - mx); s += ap[j]; }
            float inv = 1.0f / s;
            float racc = 0.f;
#pragma unroll
            for (int j = 0; j < 16; j++) {
                float a = ap[j] * inv;
                attn_out[j*DM + col] = a;
                float vv = vpt[((size_t)b*Np + sidx[qq*16 + j])*DM + col];
                float pp = pos[((size_t)(tile*128 + qq*16 + j))*DM + col];
                racc = fmaf(a, vv + pp, racc);
            }
            sres[qq*256 + col] = racc;
        }
    }
    __syncthreads();

    for (int o = tid; o < 8*DP; o += 512) {
        int qq = o >> 7, c = o & 127;
        float acc2 = fc2b[c];
        const float* sr = sres + qq*256;
#pragma unroll 4
        for (int k = 0; k < DM; k++) acc2 = fmaf(sr[k], fc2w[k*DP + c], acc2);
        int bm = bm0 + qq;
        out[(size_t)bm*DP + c] = acc2 + query[(size_t)bm*131 + 3 + c];
    }
}

// ===================== launch =====================
extern "C" void kernel_launch(void* const* d_in, const int* in_sizes, int n_in,
                              void* d_out, int out_size) {
    const float* xyz   = (const float*)d_in[0];
    const float* feat  = (const float*)d_in[1];
    const float* query = (const float*)d_in[2];
    const float* fc1w  = (const float*)d_in[3];
    const float* fc1b  = (const float*)d_in[4];
    const float* fc2w  = (const float*)d_in[5];
    const float* fc2b  = (const float*)d_in[6];
    const float* d1w   = (const float*)d_in[7];
    const float* d1b   = (const float*)d_in[8];
    const float* d2w   = (const float*)d_in[9];
    const float* d2b   = (const float*)d_in[10];
    const float* g1w   = (const float*)d_in[11];
    const float* g1b   = (const float*)d_in[12];
    const float* g2w   = (const float*)d_in[13];
    const float* g2b   = (const float*)d_in[14];
    const float* wq    = (const float*)d_in[15];
    const float* wk    = (const float*)d_in[16];
    const float* wv    = (const float*)d_in[17];
    float* out = (float*)d_out;

    static int smem_set = 0;
    if (!smem_set) {
        cudaFuncSetAttribute(tc_gemm,    cudaFuncAttributeMaxDynamicSharedMemorySize, SMEM_TOTAL);
        cudaFuncSetAttribute(g1g2_fused, cudaFuncAttributeMaxDynamicSharedMemorySize, SMEM_TOTAL);
        smem_set = 1;
    }

    __half *p_wq, *p_wf1, *p_wk, *p_wv, *p_wd2, *p_wg1, *p_wg2;
    cudaGetSymbolAddress((void**)&p_wq,  w_q);
    cudaGetSymbolAddress((void**)&p_wf1, w_f1);
    cudaGetSymbolAddress((void**)&p_wk,  w_k);
    cudaGetSymbolAddress((void**)&p_wv,  w_v);
    cudaGetSymbolAddress((void**)&p_wd2, w_d2);
    cudaGetSymbolAddress((void**)&p_wg1, w_g1);
    cudaGetSymbolAddress((void**)&p_wg2, w_g2);
    float *p_q, *p_kp, *p_vp, *p_pos;
    __half *p_qfh, *p_qfl, *p_fsh, *p_fsl, *p_xh, *p_xl, *p_hh, *p_hl,
           *p_ah, *p_al;
    cudaGetSymbolAddress((void**)&p_q,   g_q);
    cudaGetSymbolAddress((void**)&p_kp,  g_kpt);
    cudaGetSymbolAddress((void**)&p_vp,  g_vpt);
    cudaGetSymbolAddress((void**)&p_pos, g_pos);
    cudaGetSymbolAddress((void**)&p_qfh, g_qfh); cudaGetSymbolAddress((void**)&p_qfl, g_qfl);
    cudaGetSymbolAddress((void**)&p_fsh, g_fsh); cudaGetSymbolAddress((void**)&p_fsl, g_fsl);
    cudaGetSymbolAddress((void**)&p_xh,  g_xph); cudaGetSymbolAddress((void**)&p_xl,  g_xpl);
    cudaGetSymbolAddress((void**)&p_hh,  g_hhi); cudaGetSymbolAddress((void**)&p_hl,  g_hlo);
    cudaGetSymbolAddress((void**)&p_ah,  g_ahi); cudaGetSymbolAddress((void**)&p_al,  g_alo);

    knn_kernel<<<BM/8, 256>>>(xyz, query);

    wprep_kernel<<<DP, 256>>>(wq,   p_wq,  DP);
    wprep_kernel<<<DP, 256>>>(fc1w, p_wf1, DP);
    wprep_kernel<<<DM, 256>>>(wk,   p_wk,  DM);
    wprep_kernel<<<DM, 256>>>(wv,   p_wv,  DM);
    wprep_kernel<<<DM, 256>>>(d2w,  p_wd2, DM);
    wprep_kernel<<<DM, 256>>>(g1w,  p_wg1, DM);
    wprep_kernel<<<DM, 256>>>(g2w,  p_wg2, DM);

    qsplit_kernel<<<BM*DP/256, 256>>>(query, p_qfh, p_qfl);
    fsplit_kernel<<<NPT*DP/256, 256>>>(feat, p_fsh, p_fsl);
    hprep_kernel <<<BM, 256>>>(xyz, query, d1w, d1b);

    // q = query_f @ wq                     (8192 rows, fp32 -> g_q)
    tc_gemm<<<BM/128, 512, SMEM_TOTAL>>>(p_qfh, p_qfl, p_wq,
        nullptr, nullptr, nullptr, p_q, nullptr, nullptr, DP, 0);
    // x_pt = feat @ fc1 + b                (32768 rows, split)
    tc_gemm<<<NPT/128, 512, SMEM_TOTAL>>>(p_fsh, p_fsl, p_wf1,
        fc1b, nullptr, nullptr, nullptr, p_xh, p_xl, DP, 1);
    // k_pt = x_pt @ wk                     (32768 rows, fp32)
    tc_gemm<<<NPT/128, 512, SMEM_TOTAL>>>(p_xh, p_xl, p_wk,
        nullptr, nullptr, nullptr, p_kp, nullptr, nullptr, DM, 0);
    // v_pt = x_pt @ wv                     (32768 rows, fp32)
    tc_gemm<<<NPT/128, 512, SMEM_TOTAL>>>(p_xh, p_xl, p_wv,
        nullptr, nullptr, nullptr, p_vp, nullptr, nullptr, DM, 0);
    // pos = h @ d2 + b; a = q - k[gather] + pos   (131072 rows)
    tc_gemm<<<NROW/128, 512, SMEM_TOTAL>>>(p_hh, p_hl, p_wd2,
        d2b, p_q, p_kp, p_pos, p_ah, p_al, DM, 3);
    // fused: t = relu(a@g1+b); attn_pre = t@g2+b; softmax; res; fc2; residual
    g1g2_fused<<<NROW/128, 512, SMEM_TOTAL>>>(p_ah, p_al, p_wg1, g1b,
        p_wg2, g2b, fc2w, fc2b, query, p_vp, p_pos, out);
}

// round 14
// speedup vs baseline: 1.3047x; 1.1823x over previous
#include <cuda_runtime.h>
#include <cuda_fp16.h>
#include <math_constants.h>
#include <cstdint>

#define Np   8192
#define DP   128
#define DM   256
#define BM   8192           // B*M queries
#define NPT  32768          // B*Np distinct points
#define NROW 131072         // BM*16 (query,neighbor) rows
#define RES_ELEMS (BM*DP)

// ===================== PTX helpers (baseline sm_103) =====================
__device__ __forceinline__ uint32_t smem_u32(const void* p) {
    uint32_t a;
    asm("{ .reg .u64 t; cvta.to.shared.u64 t, %1; cvt.u32.u64 %0, t; }" : "=r"(a) : "l"(p));
    return a;
}
__device__ __forceinline__ void cpasync16(uint32_t dst, const void* src) {
    asm volatile("cp.async.cg.shared.global [%0], [%1], 16;" :: "r"(dst), "l"(src));
}
#define CP_COMMIT() asm volatile("cp.async.commit_group;" ::: "memory")
#define CP_WAIT(n)  asm volatile("cp.async.wait_group %0;" :: "n"(n) : "memory")
__device__ __forceinline__ void cp_wait_dyn(int n) {
    switch (n) {
        case 0: CP_WAIT(0); break;
        case 1: CP_WAIT(1); break;
        case 2: CP_WAIT(2); break;
        default: CP_WAIT(3); break;
    }
}

__device__ __forceinline__ void ldsm4(uint32_t* r, uint32_t addr) {
    asm volatile("ldmatrix.sync.aligned.m8n8.x4.shared.b16 {%0,%1,%2,%3}, [%4];"
        : "=r"(r[0]), "=r"(r[1]), "=r"(r[2]), "=r"(r[3]) : "r"(addr));
}
__device__ __forceinline__ void mma16816(float* c, const uint32_t* a, const uint32_t* b) {
    asm volatile("mma.sync.aligned.m16n8k16.row.col.f32.f16.f16.f32 "
        "{%0,%1,%2,%3}, {%4,%5,%6,%7}, {%8,%9}, {%0,%1,%2,%3};"
        : "+f"(c[0]), "+f"(c[1]), "+f"(c[2]), "+f"(c[3])
        : "r"(a[0]), "r"(a[1]), "r"(a[2]), "r"(a[3]), "r"(b[0]), "r"(b[1]));
}

// ===================== scratch =====================
__device__ int   g_knn[BM*16];
__device__ float g_q  [BM*DM];
__device__ float g_kpt[NPT*DM];
__device__ float g_vpt[NPT*DM];
__device__ __align__(16) __half g_pos[NROW*DM];
__device__ __align__(16) __half g_qf [BM*DP];
__device__ __align__(16) __half g_fs [NPT*DP];
__device__ __align__(16) __half g_xp [NPT*DM];
__device__ __align__(16) __half g_h  [NROW*DM];
__device__ __align__(16) __half g_a  [NROW*DM];
// transposed fp16 weights [N=256][K]
__device__ __align__(16) __half w_q [DM*DP];
__device__ __align__(16) __half w_f1[DM*DP];
__device__ __align__(16) __half w_k [DM*DM];
__device__ __align__(16) __half w_v [DM*DM];
__device__ __align__(16) __half w_d2[DM*DM];
__device__ __align__(16) __half w_g1[DM*DM];
__device__ __align__(16) __half w_g2[DM*DM];

// ===================== KNN =====================
__global__ void knn_kernel(const float* __restrict__ xyz,
                           const float* __restrict__ query) {
    int wip  = threadIdx.x >> 5;
    int lane = threadIdx.x & 31;
    int qi   = blockIdx.x * 8 + wip;
    int b    = qi >> 11;
    const float* qp = query + (size_t)qi * 131;
    float qx = qp[0], qy = qp[1], qz = qp[2];
    float q2 = qx*qx + qy*qy + qz*qz;
    const float* xb = xyz + (size_t)b * Np * 3;

    float bd[16]; int bi[16];
#pragma unroll
    for (int i = 0; i < 16; i++) { bd[i] = CUDART_INF_F; bi[i] = 0x7fffffff; }
    float cm = CUDART_INF_F; int cmp_ = 0;

    for (int n = lane; n < Np; n += 32) {
        float x = xb[3*n], y = xb[3*n+1], z = xb[3*n+2];
        float d = q2 + (x*x + y*y + z*z) - 2.0f*(qx*x + qy*y + qz*z);
        if (d < cm) {
#pragma unroll
            for (int i = 0; i < 16; i++) if (i == cmp_) { bd[i] = d; bi[i] = n; }
            cm = -CUDART_INF_F;
#pragma unroll
            for (int i = 0; i < 16; i++) if (bd[i] > cm) { cm = bd[i]; cmp_ = i; }
        }
    }
    for (int r = 0; r < 16; r++) {
        float md = CUDART_INF_F; int mi = 0x7fffffff;
#pragma unroll
        for (int i = 0; i < 16; i++) {
            float d = bd[i]; int id = bi[i];
            if (d < md || (d == md && id < mi)) { md = d; mi = id; }
        }
#pragma unroll
        for (int off = 16; off > 0; off >>= 1) {
            float od = __shfl_down_sync(0xffffffffu, md, off);
            int   oi = __shfl_down_sync(0xffffffffu, mi, off);
            if (od < md || (od == md && oi < mi)) { md = od; mi = oi; }
        }
        int w = __shfl_sync(0xffffffffu, mi, 0);
        if (lane == 0) g_knn[qi*16 + r] = w;
#pragma unroll
        for (int i = 0; i < 16; i++) if (bi[i] == w) bd[i] = CUDART_INF_F;
    }
}

// ===================== prep kernels =====================
__global__ void wprep_kernel(const float* __restrict__ W,
                             __half* __restrict__ T, int K) {
    int i = blockIdx.x * 256 + threadIdx.x;
    if (i >= K * DM) return;
    int k = i / DM, n = i % DM;
    T[n*K + k] = __float2half_rn(W[i]);
}

__global__ void qcvt_kernel(const float* __restrict__ query,
                            __half* __restrict__ qh) {
    int i = blockIdx.x * 256 + threadIdx.x;
    int r = i >> 7, c = i & 127;
    qh[i] = __float2half_rn(query[(size_t)r*131 + 3 + c]);
}

__global__ void fcvt_kernel(const float* __restrict__ feat,
                            __half* __restrict__ fh) {
    int i = blockIdx.x * 256 + threadIdx.x;
    fh[i] = __float2half_rn(feat[i]);
}

__global__ __launch_bounds__(256) void hprep_kernel(const float* __restrict__ xyz,
                                                    const float* __restrict__ query,
                                                    const float* __restrict__ d1w,
                                                    const float* __restrict__ d1b) {
    __shared__ float sdel[16][4];
    int bm = blockIdx.x, b = bm >> 11, tid = threadIdx.x;
    if (tid < 16) {
        int idx = g_knn[bm*16 + tid];
        const float* qp = query + (size_t)bm*131;
        const float* xp = xyz + ((size_t)b*Np + idx)*3;
        sdel[tid][0] = qp[0] - xp[0];
        sdel[tid][1] = qp[1] - xp[1];
        sdel[tid][2] = qp[2] - xp[2];
    }
    __syncthreads();
    int c = tid;
    float w0 = d1w[c], w1 = d1w[DM + c], w2 = d1w[2*DM + c], bb = d1b[c];
#pragma unroll
    for (int r = 0; r < 16; r++) {
        float v = fmaxf(fmaf(sdel[r][2], w2, fmaf(sdel[r][1], w1, fmaf(sdel[r][0], w0, bb))), 0.f);
        g_h[(size_t)(bm*16 + r)*DM + c] = __float2half_rn(v);
    }
}

// ===================== shared GEMM machinery (fp16, 1-term) ================
// stage: A +0 (18432 = 128 rows x 144B), B +18432 (36864 = 256 rows x 144B)
#define B_OFF  18432
#define STG    55296
#define SMEM_TOTAL (4*STG)          // 221184
// fused loop2: 4 t-slots (18432 each) at c*18432; B dbl-buf at:
#define SM_B2  73728

__device__ __forceinline__ void load_chunk(uint32_t sbase,
    const __half* A, const __half* B,
    int tile, int Kdim, int kc0, int tid)
{
    {
        int e = tid;                 // 1024 ops / 512 thr = 2, unrolled below
        int r = e >> 3, c = e & 7;
        size_t off = (size_t)(tile*128 + r)*Kdim + kc0 + c*8;
        cpasync16(sbase + r*144 + c*16, A + off);
        e = tid + 512; r = e >> 3; c = e & 7;
        off = (size_t)(tile*128 + r)*Kdim + kc0 + c*8;
        cpasync16(sbase + r*144 + c*16, A + off);
    }
#pragma unroll
    for (int g = 0; g < 4; g++) {
        int e = g*512 + tid;
        int n = e >> 3, c = e & 7;
        size_t off = (size_t)n*Kdim + kc0 + c*8;
        cpasync16(sbase + B_OFF + n*144 + c*16, B + off);
    }
}

// B-only load (K = DM)
__device__ __forceinline__ void load_b2(uint32_t bbase,
    const __half* B, int kc0, int tid)
{
#pragma unroll
    for (int g = 0; g < 4; g++) {
        int e = g*512 + tid;
        int n = e >> 3, c = e & 7;
        size_t off = (size_t)n*DM + kc0 + c*8;
        cpasync16(bbase + n*144 + c*16, B + off);
    }
}

// mma over one 64-wide K chunk
__device__ __forceinline__ void mma_chunk(uint32_t aB, uint32_t bB,
    uint32_t aRow, uint32_t aKoff, uint32_t bRow, uint32_t bKoff,
    int nbase, float (*acc)[8][4])
{
#pragma unroll
    for (int k16 = 0; k16 < 4; k16++) {
        uint32_t ah[2][4];
        uint32_t ab = aB + aRow*144 + k16*32 + aKoff;
        ldsm4(ah[0], ab);
        ldsm4(ah[1], ab + 16*144);
#pragma unroll
        for (int np = 0; np < 4; np++) {
            uint32_t bh[4];
            ldsm4(bh, bB + (nbase + np*16 + bRow)*144 + k16*32 + bKoff);
#pragma unroll
            for (int mf = 0; mf < 2; mf++) {
                mma16816(acc[mf][2*np],   ah[mf], bh);
                mma16816(acc[mf][2*np+1], ah[mf], bh + 2);
            }
        }
    }
}

// ===================== generic GEMM (qproj / x / k / v / pos) ==============
// epi: 0 = fp32 -> outf
//      1 = half -> outh
//      3 = pos-combined: pos half -> outl; a = q[bm] - kpt[gather] + pos -> outh
__global__ __launch_bounds__(512, 1) void tc_gemm(
    const __half* __restrict__ A, const __half* __restrict__ Bw,
    const float* __restrict__ bias,
    const float* __restrict__ qv, const float* __restrict__ kpt,
    float* __restrict__ outf,
    __half* __restrict__ outh, __half* __restrict__ outl,
    int Kdim, int epi_mode)
{
    extern __shared__ char dsm[];
    uint32_t sb = smem_u32(dsm);
    int tid = threadIdx.x, lid = tid & 31, wid = tid >> 5;
    int tile = blockIdx.x;
    int mw = wid & 3, nw = wid >> 2;
    int mbase = mw*32, nbase = nw*64;

    uint32_t aRow  = mbase + (lid & 15);
    uint32_t aKoff = ((lid >> 4) & 1) * 16;
    uint32_t bRow  = (lid & 7) + ((lid >> 4) & 1) * 8;
    uint32_t bKoff = ((lid >> 3) & 1) * 16;

    float acc[2][8][4];
#pragma unroll
    for (int i = 0; i < 2; i++)
#pragma unroll
        for (int j = 0; j < 8; j++)
#pragma unroll
            for (int e = 0; e < 4; e++) acc[i][j][e] = 0.f;

    const int nst = Kdim >> 6;
    int pre = nst < 3 ? nst : 3;
    for (int i = 0; i < pre; i++) {
        load_chunk(sb + i*STG, A, Bw, tile, Kdim, i*64, tid);
        CP_COMMIT();
    }

    for (int s = 0; s < nst; s++) {
        if (s + 3 < nst) {
            load_chunk(sb + ((s+3)&3)*STG, A, Bw, tile, Kdim, (s+3)*64, tid);
            CP_COMMIT();
            cp_wait_dyn(3);
        } else {
            cp_wait_dyn(nst - 1 - s);
        }
        __syncthreads();
        uint32_t stb = sb + (s&3)*STG;
        mma_chunk(stb, stb + B_OFF, aRow, aKoff, bRow, bKoff, nbase, acc);
        __syncthreads();
    }

    float* eb = (float*)dsm;   // [128][264]
#pragma unroll
    for (int mf = 0; mf < 2; mf++)
#pragma unroll
        for (int nf = 0; nf < 8; nf++) {
            int m = mbase + mf*16 + (lid >> 2);
            int n = nbase + nf*8 + (lid & 3)*2;
            eb[m*264 + n]     = acc[mf][nf][0];
            eb[m*264 + n + 1] = acc[mf][nf][1];
            eb[(m+8)*264 + n]     = acc[mf][nf][2];
            eb[(m+8)*264 + n + 1] = acc[mf][nf][3];
        }
    __syncthreads();

    for (int i = tid; i < 128*256; i += 512) {
        int row = i >> 8, col = i & 255;
        float v = eb[row*264 + col];
        if (bias) v += bias[col];
        size_t o = (size_t)(tile*128 + row) * DM + col;
        if (epi_mode == 0) {
            outf[o] = v;
        } else if (epi_mode == 1) {
            outh[o] = __float2half_rn(v);
        } else {  // pos-combined
            outl[o] = __float2half_rn(v);       // pos (half)
            int row_g = tile*128 + row;
            int bm = row_g >> 4, j = row_g & 15, b = bm >> 11;
            int idx = g_knn[bm*16 + j];
            float a = qv[(size_t)bm*DM + col]
                    - kpt[((size_t)b*Np + idx)*DM + col] + v;
            outh[o] = __float2half_rn(a);
        }
    }
}

// ===================== fused g1 -> g2 -> softmax/V/fc2/residual =============
__global__ __launch_bounds__(512, 1) void g1g2_fused(
    const __half* __restrict__ A,
    const __half* __restrict__ G1, const float* __restrict__ g1b,
    const __half* __restrict__ G2, const float* __restrict__ g2b,
    const float* __restrict__ fc2w, const float* __restrict__ fc2b,
    const float* __restrict__ query,
    const float* __restrict__ vpt, const __half* __restrict__ pos,
    float* __restrict__ out)
{
    extern __shared__ char dsm[];
    uint32_t sb = smem_u32(dsm);
    int tid = threadIdx.x, lid = tid & 31, wid = tid >> 5;
    int tile = blockIdx.x;
    int mw = wid & 3, nw = wid >> 2;
    int mbase = mw*32, nbase = nw*64;

    uint32_t aRow  = mbase + (lid & 15);
    uint32_t aKoff = ((lid >> 4) & 1) * 16;
    uint32_t bRow  = (lid & 7) + ((lid >> 4) & 1) * 8;
    uint32_t bKoff = ((lid >> 3) & 1) * 16;

    float acc[2][8][4];
#pragma unroll
    for (int i = 0; i < 2; i++)
#pragma unroll
        for (int j = 0; j < 8; j++)
#pragma unroll
            for (int e = 0; e < 4; e++) acc[i][j][e] = 0.f;

    // ---------------- loop1: t_pre = a @ g1 (K = 256, 4-stage) -------------
    for (int i = 0; i < 3; i++) {
        load_chunk(sb + i*STG, A, G1, tile, DM, i*64, tid);
        CP_COMMIT();
    }
    for (int s = 0; s < 4; s++) {
        if (s == 0) {
            load_chunk(sb + 3*STG, A, G1, tile, DM, 192, tid);
            CP_COMMIT();
            CP_WAIT(3);
        } else {
            cp_wait_dyn(3 - s);
        }
        __syncthreads();
        uint32_t stb = sb + (s&3)*STG;
        mma_chunk(stb, stb + B_OFF, aRow, aKoff, bRow, bKoff, nbase, acc);
        __syncthreads();
    }
    // all smem dead; acc holds t_pre

    // ---- prefetch g2 B chunks 0,1 into double buffers (dead region)
    load_b2(sb + SM_B2,         G2, 0,  tid); CP_COMMIT();
    load_b2(sb + SM_B2 + 36864, G2, 64, tid); CP_COMMIT();

    // ---- stage ALL FOUR t chunks from live acc (warp-group nw -> slot nw)
    // slot c at dsm + c*18432 (144B rows)
    {
        char* tA = dsm + nw*18432;
#pragma unroll
        for (int mf = 0; mf < 2; mf++)
#pragma unroll
            for (int nf = 0; nf < 8; nf++) {
                int r = mbase + mf*16 + (lid >> 2);
                int c = nf*8 + (lid & 3)*2;
                int gc = nbase + c;
                float v0 = fmaxf(acc[mf][nf][0] + g1b[gc],   0.f);
                float v1 = fmaxf(acc[mf][nf][1] + g1b[gc+1], 0.f);
                float v2 = fmaxf(acc[mf][nf][2] + g1b[gc],   0.f);
                float v3 = fmaxf(acc[mf][nf][3] + g1b[gc+1], 0.f);
                __half2 hp;
                hp.x = __float2half_rn(v0); hp.y = __float2half_rn(v1);
                *(uint32_t*)(tA + r*144 + c*2) = *(uint32_t*)&hp;
                hp.x = __float2half_rn(v2); hp.y = __float2half_rn(v3);
                *(uint32_t*)(tA + (r+8)*144 + c*2) = *(uint32_t*)&hp;
            }
    }

    // reset accumulators for g2
#pragma unroll
    for (int i = 0; i < 2; i++)
#pragma unroll
        for (int j = 0; j < 8; j++)
#pragma unroll
            for (int e = 0; e < 4; e++) acc[i][j][e] = 0.f;

    // ---------------- loop2: attn_pre = t @ g2 (K = 256, dbl-buffered B) ---
    for (int c4 = 0; c4 < 4; c4++) {
        if (c4 < 3) { CP_WAIT(1); } else { CP_WAIT(0); }
        __syncthreads();     // B chunk visible + t STS visible (first iter)
        mma_chunk(sb + c4*18432, sb + SM_B2 + (c4&1)*36864,
                  aRow, aKoff, bRow, bKoff, nbase, acc);
        __syncthreads();
        if (c4 + 2 < 4) {
            load_b2(sb + SM_B2 + (c4&1)*36864, G2, (c4+2)*64, tid);
            CP_COMMIT();
        }
    }

    // ---------------- epilogue: stage attn_pre, softmax, V, fc2, residual ---
    float* eb   = (float*)dsm;                 // [128][264]  (135168 B)
    float* sres = (float*)(dsm + 139264);      // [8][256]    (8192 B)
    int*   sidx = (int*)  (dsm + 147456);      // [128]
#pragma unroll
    for (int mf = 0; mf < 2; mf++)
#pragma unroll
        for (int nf = 0; nf < 8; nf++) {
            int m = mbase + mf*16 + (lid >> 2);
            int n = nbase + nf*8 + (lid & 3)*2;
            eb[m*264 + n]     = acc[mf][nf][0];
            eb[m*264 + n + 1] = acc[mf][nf][1];
            eb[(m+8)*264 + n]     = acc[mf][nf][2];
            eb[(m+8)*264 + n + 1] = acc[mf][nf][3];
        }
    int bm0 = tile * 8;
    if (tid < 128) sidx[tid] = g_knn[(bm0 + (tid >> 4))*16 + (tid & 15)];
    __syncthreads();

    {
        int qq = tid >> 6, c0 = tid & 63;
        int bm = bm0 + qq, b = bm >> 11;
        float* attn_out = out + RES_ELEMS + (size_t)bm*16*DM;
#pragma unroll
        for (int jj = 0; jj < 4; jj++) {
            int col = c0 + 64*jj;
            float bb = g2b[col];
            float ap[16];
#pragma unroll
            for (int j = 0; j < 16; j++)
                ap[j] = (eb[(qq*16 + j)*264 + col] + bb) * 0.0625f;
            float mx = ap[0];
#pragma unroll
            for (int j = 1; j < 16; j++) mx = fmaxf(mx, ap[j]);
            float s = 0.f;
#pragma unroll
            for (int j = 0; j < 16; j++) { ap[j] = __expf(ap[j] - mx); s += ap[j]; }
            float inv = 1.0f / s;
            float racc = 0.f;
#pragma unroll
            for (int j = 0; j < 16; j++) {
                float a = ap[j] * inv;
                attn_out[j*DM + col] = a;
                float vv = vpt[((size_t)b*Np + sidx[qq*16 + j])*DM + col];
                float pp = __half2float(pos[((size_t)(tile*128 + qq*16 + j))*DM + col]);
                racc = fmaf(a, vv + pp, racc);
            }
            sres[qq*256 + col] = racc;
        }
    }
    __syncthreads();

    for (int o = tid; o < 8*DP; o += 512) {
        int qq = o >> 7, c = o & 127;
        float acc2 = fc2b[c];
        const float* sr = sres + qq*256;
#pragma unroll 4
        for (int k = 0; k < DM; k++) acc2 = fmaf(sr[k], fc2w[k*DP + c], acc2);
        int bm = bm0 + qq;
        out[(size_t)bm*DP + c] = acc2 + query[(size_t)bm*131 + 3 + c];
    }
}

// ===================== launch =====================
extern "C" void kernel_launch(void* const* d_in, const int* in_sizes, int n_in,
                              void* d_out, int out_size) {
    const float* xyz   = (const float*)d_in[0];
    const float* feat  = (const float*)d_in[1];
    const float* query = (const float*)d_in[2];
    const float* fc1w  = (const float*)d_in[3];
    const float* fc1b  = (const float*)d_in[4];
    const float* fc2w  = (const float*)d_in[5];
    const float* fc2b  = (const float*)d_in[6];
    const float* d1w   = (const float*)d_in[7];
    const float* d1b   = (const float*)d_in[8];
    const float* d2w   = (const float*)d_in[9];
    const float* d2b   = (const float*)d_in[10];
    const float* g1w   = (const float*)d_in[11];
    const float* g1b   = (const float*)d_in[12];
    const float* g2w   = (const float*)d_in[13];
    const float* g2b   = (const float*)d_in[14];
    const float* wq    = (const float*)d_in[15];
    const float* wk    = (const float*)d_in[16];
    const float* wv    = (const float*)d_in[17];
    float* out = (float*)d_out;

    static int smem_set = 0;
    if (!smem_set) {
        cudaFuncSetAttribute(tc_gemm,    cudaFuncAttributeMaxDynamicSharedMemorySize, SMEM_TOTAL);
        cudaFuncSetAttribute(g1g2_fused, cudaFuncAttributeMaxDynamicSharedMemorySize, SMEM_TOTAL);
        smem_set = 1;
    }

    __half *p_wq, *p_wf1, *p_wk, *p_wv, *p_wd2, *p_wg1, *p_wg2;
    cudaGetSymbolAddress((void**)&p_wq,  w_q);
    cudaGetSymbolAddress((void**)&p_wf1, w_f1);
    cudaGetSymbolAddress((void**)&p_wk,  w_k);
    cudaGetSymbolAddress((void**)&p_wv,  w_v);
    cudaGetSymbolAddress((void**)&p_wd2, w_d2);
    cudaGetSymbolAddress((void**)&p_wg1, w_g1);
    cudaGetSymbolAddress((void**)&p_wg2, w_g2);
    float *p_q, *p_kp, *p_vp;
    __half *p_pos, *p_qf, *p_fs, *p_xp, *p_h, *p_a;
    cudaGetSymbolAddress((void**)&p_q,   g_q);
    cudaGetSymbolAddress((void**)&p_kp,  g_kpt);
    cudaGetSymbolAddress((void**)&p_vp,  g_vpt);
    cudaGetSymbolAddress((void**)&p_pos, g_pos);
    cudaGetSymbolAddress((void**)&p_qf,  g_qf);
    cudaGetSymbolAddress((void**)&p_fs,  g_fs);
    cudaGetSymbolAddress((void**)&p_xp,  g_xp);
    cudaGetSymbolAddress((void**)&p_h,   g_h);
    cudaGetSymbolAddress((void**)&p_a,   g_a);

    knn_kernel<<<BM/8, 256>>>(xyz, query);

    wprep_kernel<<<DP, 256>>>(wq,   p_wq,  DP);
    wprep_kernel<<<DP, 256>>>(fc1w, p_wf1, DP);
    wprep_kernel<<<DM, 256>>>(wk,   p_wk,  DM);
    wprep_kernel<<<DM, 256>>>(wv,   p_wv,  DM);
    wprep_kernel<<<DM, 256>>>(d2w,  p_wd2, DM);
    wprep_kernel<<<DM, 256>>>(g1w,  p_wg1, DM);
    wprep_kernel<<<DM, 256>>>(g2w,  p_wg2, DM);

    qcvt_kernel<<<BM*DP/256, 256>>>(query, p_qf);
    fcvt_kernel<<<NPT*DP/256, 256>>>(feat, p_fs);
    hprep_kernel<<<BM, 256>>>(xyz, query, d1w, d1b);

    // q = query_f @ wq                     (8192 rows, fp32 -> g_q)
    tc_gemm<<<BM/128, 512, SMEM_TOTAL>>>(p_qf, p_wq,
        nullptr, nullptr, nullptr, p_q, nullptr, nullptr, DP, 0);
    // x_pt = feat @ fc1 + b                (32768 rows, half)
    tc_gemm<<<NPT/128, 512, SMEM_TOTAL>>>(p_fs, p_wf1,
        fc1b, nullptr, nullptr, nullptr, p_xp, nullptr, DP, 1);
    // k_pt = x_pt @ wk                     (32768 rows, fp32)
    tc_gemm<<<NPT/128, 512, SMEM_TOTAL>>>(p_xp, p_wk,
        nullptr, nullptr, nullptr, p_kp, nullptr, nullptr, DM, 0);
    // v_pt = x_pt @ wv                     (32768 rows, fp32)
    tc_gemm<<<NPT/128, 512, SMEM_TOTAL>>>(p_xp, p_wv,
        nullptr, nullptr, nullptr, p_vp, nullptr, nullptr, DM, 0);
    // pos = h @ d2 + b (half); a = q - k[gather] + pos (half)   (131072 rows)
    tc_gemm<<<NROW/128, 512, SMEM_TOTAL>>>(p_h, p_wd2,
        d2b, p_q, p_kp, nullptr, p_a, p_pos, DM, 3);
    // fused: t = relu(a@g1+b); attn_pre = t@g2+b; softmax; res; fc2; residual
    g1g2_fused<<<NROW/128, 512, SMEM_TOTAL>>>(p_a, p_wg1, g1b,
        p_wg2, g2b, fc2w, fc2b, query, p_vp, p_pos, out);
}